// round 15
// baseline (speedup 1.0000x reference)
#include <cuda_runtime.h>
#include <cuda_bf16.h>
#include <stdint.h>

// HexCrop: out[b][c][u][v] = (valid ? in[b][c][cu+u-CC][cv+v-CC] : 0) * (mask ? crop_mask[u][v] : 1)
// plus crop_mask itself appended at out[B*C*K*K ...].
//
// ~96% of the hex-FOV mask is zero. Two kernels:
//  A) per-batch live-position lists (256 blocks, ~2us) -> __device__ globals
//  B) per 8-channel block: zero-fill region with aligned float4 STG, then
//     fix up only the ~35 live positions x 8 channels from the precomputed
//     list (L2-hot, shared by the 32 blocks of a batch).
// R8 showed Phase-0 recompute (8M divs/atomics) costing ~13us of ALU/issue;
// hoisting it removes that while keeping the 252MB write stream pure.

#define ENV 64
#define K   31
#define CC  15
#define KK  (K * K)            // 961
#define NB  256                // batches
#define NTHREADS 256
#define CPB 8                  // channels per block (same batch, contiguous out)
#define REGION (CPB * KK)      // 7688 floats; region start 16B-aligned
#define NVEC (REGION / 4)      // 1922 float4 stores per block
#define MAXLIVE KK             // worst case (mask off): all in-range positions

// Per-batch live lists (≈3 MB total, static __device__ scratch — no allocs).
__device__ int   g_n  [NB];
__device__ int   g_idx[NB][MAXLIVE];
__device__ int   g_off[NB][MAXLIVE];
__device__ float g_mv [NB][MAXLIVE];

// ---------------- Kernel A: build live lists, one block per batch ----------
__global__ __launch_bounds__(NTHREADS)
void hexcrop_lists_kernel(const int*   __restrict__ centers,   // [B,2] int32
                          const float* __restrict__ crop_mask, // [31,31]
                          const int*   __restrict__ mask_flag)
{
    __shared__ int s_n;
    const int b   = blockIdx.x;
    const int tid = threadIdx.x;
    if (tid == 0) s_n = 0;
    __syncthreads();

    const int cu = centers[2 * b + 0];
    const int cv = centers[2 * b + 1];
    const int use_mask = (mask_flag != nullptr && mask_flag[0] != 0) ? 1 : 0;

    for (int i = tid; i < KK; i += NTHREADS) {
        const int u = i / K;
        const int v = i - u * K;
        const int row = cu + u - CC;
        const int col = cv + v - CC;
        const float m = use_mask ? crop_mask[i] : 1.0f;
        const bool live = ((unsigned)row < ENV) & ((unsigned)col < ENV)
                          & (m != 0.0f);
        if (live) {
            const int p = atomicAdd(&s_n, 1);   // insertion order irrelevant
            g_idx[b][p] = i;
            g_off[b][p] = row * ENV + col;
            g_mv [b][p] = m;
        }
    }
    __syncthreads();
    if (tid == 0) g_n[b] = s_n;
}

// ---------------- Kernel B: fill + fixup ----------------------------------
__global__ __launch_bounds__(NTHREADS, 8)
void hexcrop_kernel(const float* __restrict__ in,          // [B,C,64,64]
                    const float* __restrict__ crop_mask,   // [31,31]
                    float*       __restrict__ out)         // [B,C,31,31] + [31,31]
{
    const int tid = threadIdx.x;
    const int blk = blockIdx.x;                 // over B*C/CPB
    const int bc0 = blk * CPB;                  // first channel index (b*C + c)
    const int b   = bc0 >> 8;                   // C == 256

    float* dst = out + (size_t)bc0 * KK;   // contiguous REGION floats, 16B-aligned

    // Phase A: zero-fill the region with aligned float4 stores.
    const float4 z = make_float4(0.f, 0.f, 0.f, 0.f);
    #pragma unroll 8
    for (int t = tid; t < NVEC; t += NTHREADS)
        reinterpret_cast<float4*>(dst)[t] = z;

    __syncthreads();   // fill complete before cross-thread fixups

    // Phase B: fix up live positions across CPB channels from the list.
    const int n = g_n[b];                        // broadcast, L2-hot
    const int total = n * CPB;
    const float* src0 = in + (size_t)bc0 * (ENV * ENV);
    const int* __restrict__ idx = g_idx[b];
    const int* __restrict__ off = g_off[b];
    const float* __restrict__ mv = g_mv[b];

    for (int t = tid; t < total; t += NTHREADS) {
        const int c = t / n;
        const int p = t - c * n;
        const float val = __ldg(src0 + (size_t)c * (ENV * ENV) + off[p]) * mv[p];
        dst[(size_t)c * KK + idx[p]] = val;
    }

    // Block 0 writes the raw mask tail (second tuple element).
    if (blk == 0) {
        float* tail = out + (size_t)gridDim.x * REGION;
        for (int i = tid; i < KK; i += NTHREADS)
            tail[i] = crop_mask[i];
    }
}

extern "C" void kernel_launch(void* const* d_in, const int* in_sizes, int n_in,
                              void* d_out, int out_size)
{
    const float* in       = (const float*)d_in[0];   // input_tensor [256,256,64,64] f32
    const int*   centers  = (const int*)  d_in[1];   // center_positions [256,2] i32
    const float* cmask    = (const float*)d_in[2];   // crop_mask [31,31] f32
    const int*   maskflag = (n_in > 3) ? (const int*)d_in[3] : nullptr;

    const int B = in_sizes[1] / 2;                    // 256
    const int C = in_sizes[0] / (B * ENV * ENV);      // 256

    float* out = (float*)d_out;
    hexcrop_lists_kernel<<<B, NTHREADS>>>(centers, cmask, maskflag);
    hexcrop_kernel<<<(B * C) / CPB, NTHREADS>>>(in, cmask, out);
}